// round 1
// baseline (speedup 1.0000x reference)
#include <cuda_runtime.h>
#include <cuda_bf16.h>
#include <cstdint>

// Problem constants
static constexpr int BB = 2;
static constexpr int LSEQ = 2048;
static constexpr int DM = 768;        // d_model
static constexpr int DI = 1536;       // d_inner
static constexpr int DS = 16;         // d_state
static constexpr int RK = 48;         // dt_rank
static constexpr int KC = 4;          // conv kernel
static constexpr int XD = RK + 2*DS;  // 80
static constexpr int MROWS = BB * LSEQ;  // 4096

// Scratch (no cudaMalloc allowed)
__device__ float g_xp  [MROWS * DI];
__device__ float g_z   [MROWS * DI];
__device__ float g_xc  [MROWS * DI];
__device__ float g_xdbl[MROWS * XD];
__device__ float g_dt  [MROWS * DI];
__device__ float g_y   [MROWS * DI];

__device__ __forceinline__ float siluf(float v) {
    return v / (1.f + __expf(-v));
}
__device__ __forceinline__ float softplusf(float v) {
    if (v > 20.f) return v;
    if (v < -20.f) return __expf(v);
    return log1pf(__expf(v));
}

// ---------------------------------------------------------------------------
// Generic fp32 SGEMM: C[M,N] = A[M,K] @ W[N,K]^T  (both row-major)
// BM=BN=128, BK=16, 256 threads, 8x8 per thread. M%128==0, N%128==0, K%16==0.
// EPI==0: plain store to C0 (ld = N)
// EPI==1: split columns: n < DI -> C0[m*DI + n], else C1[m*DI + n-DI]
// ---------------------------------------------------------------------------
template<int EPI>
__global__ __launch_bounds__(256)
void sgemm_tt(const float* __restrict__ A, const float* __restrict__ W,
              float* __restrict__ C0, float* __restrict__ C1,
              int M, int N, int K)
{
    __shared__ float As[16][128];
    __shared__ float Ws[16][128];

    const int tid = threadIdx.x;
    const int bm = blockIdx.y * 128;
    const int bn = blockIdx.x * 128;

    const int lr = tid >> 2;          // 0..63
    const int lc = (tid & 3) * 4;     // 0,4,8,12
    const int tx = tid & 15;
    const int ty = tid >> 4;

    float acc[8][8];
#pragma unroll
    for (int i = 0; i < 8; ++i)
#pragma unroll
        for (int j = 0; j < 8; ++j) acc[i][j] = 0.f;

    const float* Ap = A + (size_t)bm * K + lc;
    const float* Wp = W + (size_t)bn * K + lc;

    for (int k0 = 0; k0 < K; k0 += 16) {
        float4 a0 = *(const float4*)(Ap + (size_t)lr * K + k0);
        float4 a1 = *(const float4*)(Ap + (size_t)(lr + 64) * K + k0);
        float4 w0 = *(const float4*)(Wp + (size_t)lr * K + k0);
        float4 w1 = *(const float4*)(Wp + (size_t)(lr + 64) * K + k0);

        __syncthreads();
        As[lc+0][lr] = a0.x; As[lc+1][lr] = a0.y; As[lc+2][lr] = a0.z; As[lc+3][lr] = a0.w;
        As[lc+0][lr+64] = a1.x; As[lc+1][lr+64] = a1.y; As[lc+2][lr+64] = a1.z; As[lc+3][lr+64] = a1.w;
        Ws[lc+0][lr] = w0.x; Ws[lc+1][lr] = w0.y; Ws[lc+2][lr] = w0.z; Ws[lc+3][lr] = w0.w;
        Ws[lc+0][lr+64] = w1.x; Ws[lc+1][lr+64] = w1.y; Ws[lc+2][lr+64] = w1.z; Ws[lc+3][lr+64] = w1.w;
        __syncthreads();

#pragma unroll
        for (int k = 0; k < 16; ++k) {
            float4 fa0 = *(const float4*)&As[k][ty*8];
            float4 fa1 = *(const float4*)&As[k][ty*8+4];
            float4 fb0 = *(const float4*)&Ws[k][tx*8];
            float4 fb1 = *(const float4*)&Ws[k][tx*8+4];
            float ra[8] = {fa0.x,fa0.y,fa0.z,fa0.w,fa1.x,fa1.y,fa1.z,fa1.w};
            float rb[8] = {fb0.x,fb0.y,fb0.z,fb0.w,fb1.x,fb1.y,fb1.z,fb1.w};
#pragma unroll
            for (int i = 0; i < 8; ++i)
#pragma unroll
                for (int j = 0; j < 8; ++j)
                    acc[i][j] = fmaf(ra[i], rb[j], acc[i][j]);
        }
    }

    // epilogue
    if (EPI == 0) {
#pragma unroll
        for (int i = 0; i < 8; ++i) {
            int m = bm + ty*8 + i;
            float* cp = C0 + (size_t)m * N + bn + tx*8;
            float4 v0 = make_float4(acc[i][0], acc[i][1], acc[i][2], acc[i][3]);
            float4 v1 = make_float4(acc[i][4], acc[i][5], acc[i][6], acc[i][7]);
            *(float4*)(cp) = v0;
            *(float4*)(cp + 4) = v1;
        }
    } else {
        float* base = (bn < DI) ? C0 : C1;
        int ncol = (bn < DI) ? bn : (bn - DI);
#pragma unroll
        for (int i = 0; i < 8; ++i) {
            int m = bm + ty*8 + i;
            float* cp = base + (size_t)m * DI + ncol + tx*8;
            float4 v0 = make_float4(acc[i][0], acc[i][1], acc[i][2], acc[i][3]);
            float4 v1 = make_float4(acc[i][4], acc[i][5], acc[i][6], acc[i][7]);
            *(float4*)(cp) = v0;
            *(float4*)(cp + 4) = v1;
        }
    }
}

// ---------------------------------------------------------------------------
// Depthwise causal conv1d (K=4, left-pad 3) + bias + SiLU
// xc[b,l,d] = silu( sum_k xp[b, l+k-3, d] * cw[d*4+k] + cb[d] )
// ---------------------------------------------------------------------------
__global__ __launch_bounds__(256)
void conv_silu_kernel(const float* __restrict__ xp, const float* __restrict__ cw,
                      const float* __restrict__ cb, float* __restrict__ xc)
{
    int idx = blockIdx.x * blockDim.x + threadIdx.x;
    if (idx >= MROWS * DI) return;
    int d = idx % DI;
    int row = idx / DI;          // b*LSEQ + l
    int l = row % LSEQ;

    float w0 = cw[d*4+0], w1 = cw[d*4+1], w2 = cw[d*4+2], w3 = cw[d*4+3];
    float acc = cb[d];
    const float* p = xp + (size_t)(row) * DI + d;   // element (row, d)
    if (l >= 3) acc += p[-3*DI] * w0;
    if (l >= 2) acc += p[-2*DI] * w1;
    if (l >= 1) acc += p[-1*DI] * w2;
    acc += p[0] * w3;
    xc[idx] = siluf(acc);
}

// ---------------------------------------------------------------------------
// x_dbl = xc @ x_proj_w^T   [4096,1536] x [80,1536]^T -> [4096,80]
// BM=32 rows/block, BK=32, 256 threads, 2x5 micro-tile. grid = 128.
// ---------------------------------------------------------------------------
__global__ __launch_bounds__(256)
void gemm_xdbl(const float* __restrict__ A, const float* __restrict__ W,
               float* __restrict__ C)
{
    __shared__ float As[32][33];
    __shared__ float Ws[32][81];
    const int tid = threadIdx.x;
    const int bm = blockIdx.x * 32;
    const int tr = tid >> 4;      // 0..15 -> rows tr*2, tr*2+1
    const int tc = tid & 15;      // 0..15 -> cols tc*5 .. tc*5+4
    const int c = tid & 31;
    const int r0 = tid >> 5;      // 0..7

    float acc0[5] = {0,0,0,0,0};
    float acc1[5] = {0,0,0,0,0};

    for (int k0 = 0; k0 < DI; k0 += 32) {
        __syncthreads();
#pragma unroll
        for (int rr = r0; rr < 32; rr += 8)
            As[c][rr] = A[(size_t)(bm + rr) * DI + k0 + c];
#pragma unroll
        for (int n = r0; n < 80; n += 8)
            Ws[c][n] = W[(size_t)n * DI + k0 + c];
        __syncthreads();
#pragma unroll
        for (int k = 0; k < 32; ++k) {
            float a0 = As[k][tr*2];
            float a1 = As[k][tr*2+1];
#pragma unroll
            for (int j = 0; j < 5; ++j) {
                float w = Ws[k][tc*5 + j];
                acc0[j] = fmaf(a0, w, acc0[j]);
                acc1[j] = fmaf(a1, w, acc1[j]);
            }
        }
    }
#pragma unroll
    for (int j = 0; j < 5; ++j) {
        C[(size_t)(bm + tr*2    ) * XD + tc*5 + j] = acc0[j];
        C[(size_t)(bm + tr*2 + 1) * XD + tc*5 + j] = acc1[j];
    }
}

// ---------------------------------------------------------------------------
// dt = softplus( x_dbl[:, :48] @ dt_proj_w^T + dt_proj_b )   -> [4096,1536]
// 16 rows/block, column chunks of 128, 256 threads. grid = 256.
// ---------------------------------------------------------------------------
__global__ __launch_bounds__(256)
void gemm_dt(const float* __restrict__ xdbl, const float* __restrict__ Wt,
             const float* __restrict__ bt, float* __restrict__ dt)
{
    __shared__ float s_in[16][48];
    __shared__ float s_w[48][128];
    const int tid = threadIdx.x;
    const int m0 = blockIdx.x * 16;

    for (int i = tid; i < 16*48; i += 256) {
        int r = i / 48, q = i % 48;
        s_in[r][q] = xdbl[(size_t)(m0 + r) * XD + q];
    }

    const int col = tid & 127;
    const int rh = tid >> 7;   // 0 or 1

    for (int d0 = 0; d0 < DI; d0 += 128) {
        __syncthreads();
        for (int i = tid; i < 128*48; i += 256) {
            int cc = i / 48, q = i % 48;
            s_w[q][cc] = Wt[(size_t)(d0 + cc) * RK + q];
        }
        __syncthreads();
        float bias = bt[d0 + col];
#pragma unroll
        for (int rr = 0; rr < 8; ++rr) {
            int row = rh*8 + rr;
            float acc = bias;
#pragma unroll
            for (int q = 0; q < 48; ++q)
                acc = fmaf(s_in[row][q], s_w[q][col], acc);
            dt[(size_t)(m0 + row) * DI + d0 + col] = softplusf(acc);
        }
    }
}

// ---------------------------------------------------------------------------
// Selective scan. 16 lanes per (b,d) channel, one state per lane.
// h_l = exp(dt*A[d,s]) * h_{l-1} + dt*xc*B[l,s];  y_l = sum_s h_l * C[l,s]
// then y = (y + xc*D[d]) * silu(z). 128 threads = 8 channels/block; grid 384.
// ---------------------------------------------------------------------------
__global__ __launch_bounds__(128)
void scan_kernel(const float* __restrict__ xdbl, const float* __restrict__ dt,
                 const float* __restrict__ xc, const float* __restrict__ z,
                 const float* __restrict__ A_log, const float* __restrict__ Dp,
                 float* __restrict__ y)
{
    const int lane16 = threadIdx.x & 15;
    const int grp = threadIdx.x >> 4;
    const int ch = blockIdx.x * 8 + grp;     // 0..3071
    const int b = ch / DI;
    const int d = ch % DI;

    const float A = -__expf(A_log[d*DS + lane16]);
    const float Dv = Dp[d];
    float h = 0.f;

    const float* dt_p = dt + (size_t)b * LSEQ * DI + d;
    const float* xc_p = xc + (size_t)b * LSEQ * DI + d;
    const float* z_p  = z  + (size_t)b * LSEQ * DI + d;
    const float* xd_p = xdbl + (size_t)b * LSEQ * XD;
    float* y_p = y + (size_t)b * LSEQ * DI + d;

#pragma unroll 4
    for (int l = 0; l < LSEQ; ++l) {
        float dtv = __ldg(dt_p);
        float xcv = __ldg(xc_p);
        float Bv  = __ldg(xd_p + RK + lane16);
        float Cv  = __ldg(xd_p + RK + DS + lane16);

        float a = __expf(dtv * A);
        h = fmaf(a, h, dtv * xcv * Bv);
        float p = h * Cv;
        p += __shfl_xor_sync(0xffffffffu, p, 1);
        p += __shfl_xor_sync(0xffffffffu, p, 2);
        p += __shfl_xor_sync(0xffffffffu, p, 4);
        p += __shfl_xor_sync(0xffffffffu, p, 8);
        if (lane16 == 0) {
            float zv = __ldg(z_p);
            *y_p = (p + xcv * Dv) * siluf(zv);
        }
        dt_p += DI; xc_p += DI; z_p += DI; y_p += DI; xd_p += XD;
    }
}

// ---------------------------------------------------------------------------
extern "C" void kernel_launch(void* const* d_in, const int* in_sizes, int n_in,
                              void* d_out, int out_size)
{
    const float* x          = (const float*)d_in[0];
    const float* in_proj_w  = (const float*)d_in[1];
    const float* conv_w     = (const float*)d_in[2];
    const float* conv_b     = (const float*)d_in[3];
    const float* A_log      = (const float*)d_in[4];
    const float* D_param    = (const float*)d_in[5];
    const float* x_proj_w   = (const float*)d_in[6];
    const float* dt_proj_w  = (const float*)d_in[7];
    const float* dt_proj_b  = (const float*)d_in[8];
    const float* out_proj_w = (const float*)d_in[9];
    float* out = (float*)d_out;

    float *xp, *zb, *xc, *xdbl, *dtb, *yb;
    cudaGetSymbolAddress((void**)&xp,   g_xp);
    cudaGetSymbolAddress((void**)&zb,   g_z);
    cudaGetSymbolAddress((void**)&xc,   g_xc);
    cudaGetSymbolAddress((void**)&xdbl, g_xdbl);
    cudaGetSymbolAddress((void**)&dtb,  g_dt);
    cudaGetSymbolAddress((void**)&yb,   g_y);

    // 1. xz = x @ in_proj_w^T, split -> xp, z
    {
        dim3 grid(2*DI/128, MROWS/128);
        sgemm_tt<1><<<grid, 256>>>(x, in_proj_w, xp, zb, MROWS, 2*DI, DM);
    }
    // 2. causal depthwise conv + bias + SiLU -> xc
    {
        int total = MROWS * DI;
        conv_silu_kernel<<<(total + 255)/256, 256>>>(xp, conv_w, conv_b, xc);
    }
    // 3. x_dbl = xc @ x_proj_w^T
    gemm_xdbl<<<MROWS/32, 256>>>(xc, x_proj_w, xdbl);
    // 4. dt = softplus(dt_low @ dt_proj_w^T + b)
    gemm_dt<<<MROWS/16, 256>>>(xdbl, dt_proj_w, dt_proj_b, dtb);
    // 5. selective scan + gating -> y
    scan_kernel<<<(BB*DI)/8, 128>>>(xdbl, dtb, xc, zb, A_log, D_param, yb);
    // 6. out = y @ out_proj_w^T
    {
        dim3 grid(DM/128, MROWS/128);
        sgemm_tt<0><<<grid, 256>>>(yb, out_proj_w, out, nullptr, MROWS, DM, DI);
    }
}

// round 2
// speedup vs baseline: 2.8979x; 2.8979x over previous
#include <cuda_runtime.h>
#include <cuda_bf16.h>
#include <cstdint>

// Problem constants
static constexpr int BB = 2;
static constexpr int LSEQ = 2048;
static constexpr int DM = 768;        // d_model
static constexpr int DI = 1536;       // d_inner
static constexpr int DS = 16;         // d_state
static constexpr int RK = 48;         // dt_rank
static constexpr int XD = RK + 2*DS;  // 80
static constexpr int MROWS = BB * LSEQ;  // 4096

// Scan chunking
static constexpr int NCH = 8;
static constexpr int CHUNK = LSEQ / NCH;   // 256
static constexpr int NCHAN = BB * DI;      // 3072

// Scratch (no cudaMalloc allowed)
__device__ float g_xp  [MROWS * DI];
__device__ float g_z   [MROWS * DI];
__device__ float g_xc  [MROWS * DI];
__device__ float g_xdbl[MROWS * XD];
__device__ float g_dt  [MROWS * DI];
__device__ float g_y   [MROWS * DI];
__device__ float g_P   [NCHAN * NCH * DS];
__device__ float g_H   [NCHAN * NCH * DS];
__device__ float g_Hin [NCHAN * NCH * DS];

__device__ __forceinline__ float siluf(float v) {
    return v / (1.f + __expf(-v));
}
__device__ __forceinline__ float softplusf(float v) {
    if (v > 20.f) return v;
    if (v < -20.f) return __expf(v);
    return log1pf(__expf(v));
}
__device__ __forceinline__ uint32_t f2tf32(float f) {
    uint32_t r;
    asm("cvt.rna.tf32.f32 %0, %1;" : "=r"(r) : "f"(f));
    return r;
}
__device__ __forceinline__ void mma_tf32(float c[4], uint32_t a0, uint32_t a1,
                                         uint32_t a2, uint32_t a3,
                                         uint32_t b0, uint32_t b1) {
    asm volatile(
        "mma.sync.aligned.m16n8k8.row.col.f32.tf32.tf32.f32 "
        "{%0,%1,%2,%3}, {%4,%5,%6,%7}, {%8,%9}, {%0,%1,%2,%3};"
        : "+f"(c[0]), "+f"(c[1]), "+f"(c[2]), "+f"(c[3])
        : "r"(a0), "r"(a1), "r"(a2), "r"(a3), "r"(b0), "r"(b1));
}

// ---------------------------------------------------------------------------
// tf32 tensor-core GEMM: C[M,N] = A[M,K] @ W[N,K]^T  (row-major)
// Block 128x128, k-tile 32, 8 warps (2M x 4N), warp tile 64x32.
// Each warp: 4 m16 tiles x 4 n8 tiles, 4 k-substeps of 8.
// EPI==0: plain store to C0 (ld = N)
// EPI==1: n < DI -> C0[m*DI+n], else C1[m*DI+n-DI]
// Requires M%128==0, N%128==0, K%32==0.
// ---------------------------------------------------------------------------
template<int EPI>
__global__ __launch_bounds__(256)
void gemm_tf32(const float* __restrict__ A, const float* __restrict__ W,
               float* __restrict__ C0, float* __restrict__ C1,
               int M, int N, int K)
{
    __shared__ uint32_t As[128][36];   // [row][k], stride 36 -> conflict-free frag loads
    __shared__ uint32_t Ws[128][36];   // [n][k]

    const int tid  = threadIdx.x;
    const int lane = tid & 31;
    const int wid  = tid >> 5;
    const int wm   = wid & 1;          // 0..1  (M)
    const int wn   = wid >> 1;         // 0..3  (N)
    const int bm   = blockIdx.y * 128;
    const int bn   = blockIdx.x * 128;

    const int ldr = tid >> 3;          // 0..31 (row within pass)
    const int ldc = (tid & 7) * 4;     // col*4

    float c[4][4][4];
#pragma unroll
    for (int i = 0; i < 4; ++i)
#pragma unroll
        for (int j = 0; j < 4; ++j)
#pragma unroll
            for (int q = 0; q < 4; ++q) c[i][j][q] = 0.f;

    for (int k0 = 0; k0 < K; k0 += 32) {
        // fetch global -> regs
        float4 av[4], wv[4];
#pragma unroll
        for (int p = 0; p < 4; ++p) {
            int r = ldr + p * 32;
            av[p] = *(const float4*)(A + (size_t)(bm + r) * K + k0 + ldc);
            wv[p] = *(const float4*)(W + (size_t)(bn + r) * K + k0 + ldc);
        }
        __syncthreads();
#pragma unroll
        for (int p = 0; p < 4; ++p) {
            int r = ldr + p * 32;
            As[r][ldc+0] = f2tf32(av[p].x); As[r][ldc+1] = f2tf32(av[p].y);
            As[r][ldc+2] = f2tf32(av[p].z); As[r][ldc+3] = f2tf32(av[p].w);
            Ws[r][ldc+0] = f2tf32(wv[p].x); Ws[r][ldc+1] = f2tf32(wv[p].y);
            Ws[r][ldc+2] = f2tf32(wv[p].z); Ws[r][ldc+3] = f2tf32(wv[p].w);
        }
        __syncthreads();

        const int g = lane >> 2;
#pragma unroll
        for (int ks = 0; ks < 4; ++ks) {
            const int kk = ks * 8 + (lane & 3);
            uint32_t a[4][4], b[4][2];
#pragma unroll
            for (int mt = 0; mt < 4; ++mt) {
                int r = wm * 64 + mt * 16 + g;
                a[mt][0] = As[r][kk];     a[mt][1] = As[r + 8][kk];
                a[mt][2] = As[r][kk + 4]; a[mt][3] = As[r + 8][kk + 4];
            }
#pragma unroll
            for (int nt = 0; nt < 4; ++nt) {
                int n = wn * 32 + nt * 8 + g;
                b[nt][0] = Ws[n][kk]; b[nt][1] = Ws[n][kk + 4];
            }
#pragma unroll
            for (int mt = 0; mt < 4; ++mt)
#pragma unroll
                for (int nt = 0; nt < 4; ++nt)
                    mma_tf32(c[mt][nt], a[mt][0], a[mt][1], a[mt][2], a[mt][3],
                             b[nt][0], b[nt][1]);
        }
    }

    // epilogue
    const int g = lane >> 2;
    const int q2 = (lane & 3) * 2;
    float* base;
    int ncol0, ldc_out;
    if (EPI == 0) { base = C0; ncol0 = bn; ldc_out = N; }
    else {
        base = (bn < DI) ? C0 : C1;
        ncol0 = (bn < DI) ? bn : (bn - DI);
        ldc_out = DI;
    }
#pragma unroll
    for (int mt = 0; mt < 4; ++mt) {
#pragma unroll
        for (int nt = 0; nt < 4; ++nt) {
            int row = bm + wm * 64 + mt * 16 + g;
            int col = ncol0 + wn * 32 + nt * 8 + q2;
            float2 v0 = make_float2(c[mt][nt][0], c[mt][nt][1]);
            float2 v1 = make_float2(c[mt][nt][2], c[mt][nt][3]);
            *(float2*)(base + (size_t)row * ldc_out + col) = v0;
            *(float2*)(base + (size_t)(row + 8) * ldc_out + col) = v1;
        }
    }
}

// ---------------------------------------------------------------------------
// Depthwise causal conv1d (K=4, left-pad 3) + bias + SiLU
// ---------------------------------------------------------------------------
__global__ __launch_bounds__(256)
void conv_silu_kernel(const float* __restrict__ xp, const float* __restrict__ cw,
                      const float* __restrict__ cb, float* __restrict__ xc)
{
    int idx = blockIdx.x * blockDim.x + threadIdx.x;
    if (idx >= MROWS * DI) return;
    int d = idx % DI;
    int row = idx / DI;
    int l = row % LSEQ;

    float w0 = cw[d*4+0], w1 = cw[d*4+1], w2 = cw[d*4+2], w3 = cw[d*4+3];
    float acc = cb[d];
    const float* p = xp + (size_t)row * DI + d;
    if (l >= 3) acc += p[-3*DI] * w0;
    if (l >= 2) acc += p[-2*DI] * w1;
    if (l >= 1) acc += p[-1*DI] * w2;
    acc += p[0] * w3;
    xc[idx] = siluf(acc);
}

// ---------------------------------------------------------------------------
// x_dbl = xc @ x_proj_w^T   [4096,1536] x [80,1536]^T -> [4096,80]
// ---------------------------------------------------------------------------
__global__ __launch_bounds__(256)
void gemm_xdbl(const float* __restrict__ A, const float* __restrict__ W,
               float* __restrict__ C)
{
    __shared__ float As[32][33];
    __shared__ float Ws[32][81];
    const int tid = threadIdx.x;
    const int bm = blockIdx.x * 32;
    const int tr = tid >> 4;
    const int tc = tid & 15;
    const int cc = tid & 31;
    const int r0 = tid >> 5;

    float acc0[5] = {0,0,0,0,0};
    float acc1[5] = {0,0,0,0,0};

    for (int k0 = 0; k0 < DI; k0 += 32) {
        __syncthreads();
#pragma unroll
        for (int rr = r0; rr < 32; rr += 8)
            As[cc][rr] = A[(size_t)(bm + rr) * DI + k0 + cc];
#pragma unroll
        for (int n = r0; n < 80; n += 8)
            Ws[cc][n] = W[(size_t)n * DI + k0 + cc];
        __syncthreads();
#pragma unroll
        for (int k = 0; k < 32; ++k) {
            float a0 = As[k][tr*2];
            float a1 = As[k][tr*2+1];
#pragma unroll
            for (int j = 0; j < 5; ++j) {
                float w = Ws[k][tc*5 + j];
                acc0[j] = fmaf(a0, w, acc0[j]);
                acc1[j] = fmaf(a1, w, acc1[j]);
            }
        }
    }
#pragma unroll
    for (int j = 0; j < 5; ++j) {
        C[(size_t)(bm + tr*2    ) * XD + tc*5 + j] = acc0[j];
        C[(size_t)(bm + tr*2 + 1) * XD + tc*5 + j] = acc1[j];
    }
}

// ---------------------------------------------------------------------------
// dt = softplus( x_dbl[:, :48] @ dt_proj_w^T + b )  -> [4096,1536]
// Block: 64 rows x 128 cols, 256 threads, 8x4 micro-tile.
// grid = (12, 64)
// ---------------------------------------------------------------------------
__global__ __launch_bounds__(256)
void gemm_dt(const float* __restrict__ xdbl, const float* __restrict__ Wt,
             const float* __restrict__ bt, float* __restrict__ dt)
{
    __shared__ float s_in[64][49];
    __shared__ float s_w[48][128];
    const int tid = threadIdx.x;
    const int m0 = blockIdx.y * 64;
    const int n0 = blockIdx.x * 128;

    for (int i = tid; i < 64*48; i += 256) {
        int r = i / 48, q = i % 48;
        s_in[r][q] = xdbl[(size_t)(m0 + r) * XD + q];
    }
    for (int i = tid; i < 128*48; i += 256) {
        int col = i & 127, q = i >> 7;
        s_w[q][col] = Wt[(size_t)(n0 + col) * RK + q];
    }
    __syncthreads();

    const int col = (tid & 31) * 4;
    const int row0 = (tid >> 5) * 8;

    float acc[8][4];
    {
        float4 b4 = *(const float4*)(bt + n0 + col);
#pragma unroll
        for (int r = 0; r < 8; ++r) {
            acc[r][0] = b4.x; acc[r][1] = b4.y; acc[r][2] = b4.z; acc[r][3] = b4.w;
        }
    }
#pragma unroll
    for (int q = 0; q < 48; ++q) {
        float4 w4 = *(const float4*)&s_w[q][col];
#pragma unroll
        for (int r = 0; r < 8; ++r) {
            float a = s_in[row0 + r][q];
            acc[r][0] = fmaf(a, w4.x, acc[r][0]);
            acc[r][1] = fmaf(a, w4.y, acc[r][1]);
            acc[r][2] = fmaf(a, w4.z, acc[r][2]);
            acc[r][3] = fmaf(a, w4.w, acc[r][3]);
        }
    }
#pragma unroll
    for (int r = 0; r < 8; ++r) {
        float* p = dt + (size_t)(m0 + row0 + r) * DI + n0 + col;
        p[0] = softplusf(acc[r][0]);
        p[1] = softplusf(acc[r][1]);
        p[2] = softplusf(acc[r][2]);
        p[3] = softplusf(acc[r][3]);
    }
}

// ---------------------------------------------------------------------------
// Chunked selective scan, pass 1: per (channel, chunk) compute
//   P = prod_l a_l  and  H = local scan final state (h0 = 0)
// 16 lanes per unit (one state each). 128 threads = 8 units/block.
// units = NCHAN * NCH = 24576 -> grid 3072.
// ---------------------------------------------------------------------------
__global__ __launch_bounds__(128)
void scan_pass1(const float* __restrict__ xdbl, const float* __restrict__ dt,
                const float* __restrict__ xc, const float* __restrict__ A_log,
                float* __restrict__ P, float* __restrict__ H)
{
    const int s = threadIdx.x & 15;
    const int unit = blockIdx.x * 8 + (threadIdx.x >> 4);
    const int ch = unit >> 3;          // 0..3071
    const int c  = unit & 7;           // chunk
    const int b = ch / DI;
    const int d = ch % DI;

    const float A = -__expf(A_log[d*DS + s]);
    float h = 0.f, Pv = 1.f;

    const int row0 = b * LSEQ + c * CHUNK;
    const float* dt_p = dt + (size_t)row0 * DI + d;
    const float* xc_p = xc + (size_t)row0 * DI + d;
    const float* xd_p = xdbl + (size_t)row0 * XD;

#pragma unroll 4
    for (int l = 0; l < CHUNK; ++l) {
        float dtv = __ldg(dt_p);
        float xcv = __ldg(xc_p);
        float Bv  = __ldg(xd_p + RK + s);
        float a = __expf(dtv * A);
        Pv *= a;
        h = fmaf(a, h, dtv * xcv * Bv);
        dt_p += DI; xc_p += DI; xd_p += XD;
    }
    P[unit * DS + s] = Pv;
    H[unit * DS + s] = h;
}

// ---------------------------------------------------------------------------
// Combine: serial scan over the 8 chunk transitions per (channel, state).
// Hin[ch][c][s] = incoming state for chunk c. 49152 threads.
// ---------------------------------------------------------------------------
__global__ __launch_bounds__(256)
void scan_combine(const float* __restrict__ P, const float* __restrict__ H,
                  float* __restrict__ Hin)
{
    int idx = blockIdx.x * blockDim.x + threadIdx.x;
    if (idx >= NCHAN * DS) return;
    int ch = idx >> 4;
    int s = idx & 15;
    float run = 0.f;
#pragma unroll
    for (int c = 0; c < NCH; ++c) {
        int o = (ch * NCH + c) * DS + s;
        Hin[o] = run;
        run = fmaf(P[o], run, H[o]);
    }
}

// ---------------------------------------------------------------------------
// Pass 2: replay each chunk from its correct incoming state, emit
//   y = (sum_s h*C + xc*D) * silu(z)
// ---------------------------------------------------------------------------
__global__ __launch_bounds__(128)
void scan_pass2(const float* __restrict__ xdbl, const float* __restrict__ dt,
                const float* __restrict__ xc, const float* __restrict__ z,
                const float* __restrict__ A_log, const float* __restrict__ Dp,
                const float* __restrict__ Hin, float* __restrict__ y)
{
    const int s = threadIdx.x & 15;
    const int unit = blockIdx.x * 8 + (threadIdx.x >> 4);
    const int ch = unit >> 3;
    const int c  = unit & 7;
    const int b = ch / DI;
    const int d = ch % DI;

    const float A = -__expf(A_log[d*DS + s]);
    const float Dv = Dp[d];
    float h = Hin[unit * DS + s];

    const int row0 = b * LSEQ + c * CHUNK;
    const float* dt_p = dt + (size_t)row0 * DI + d;
    const float* xc_p = xc + (size_t)row0 * DI + d;
    const float* z_p  = z  + (size_t)row0 * DI + d;
    const float* xd_p = xdbl + (size_t)row0 * XD;
    float* y_p = y + (size_t)row0 * DI + d;

#pragma unroll 4
    for (int l = 0; l < CHUNK; ++l) {
        float dtv = __ldg(dt_p);
        float xcv = __ldg(xc_p);
        float Bv  = __ldg(xd_p + RK + s);
        float Cv  = __ldg(xd_p + RK + DS + s);

        float a = __expf(dtv * A);
        h = fmaf(a, h, dtv * xcv * Bv);
        float p = h * Cv;
        p += __shfl_xor_sync(0xffffffffu, p, 1);
        p += __shfl_xor_sync(0xffffffffu, p, 2);
        p += __shfl_xor_sync(0xffffffffu, p, 4);
        p += __shfl_xor_sync(0xffffffffu, p, 8);
        if (s == 0) {
            float zv = __ldg(z_p);
            *y_p = (p + xcv * Dv) * siluf(zv);
        }
        dt_p += DI; xc_p += DI; z_p += DI; y_p += DI; xd_p += XD;
    }
}

// ---------------------------------------------------------------------------
extern "C" void kernel_launch(void* const* d_in, const int* in_sizes, int n_in,
                              void* d_out, int out_size)
{
    const float* x          = (const float*)d_in[0];
    const float* in_proj_w  = (const float*)d_in[1];
    const float* conv_w     = (const float*)d_in[2];
    const float* conv_b     = (const float*)d_in[3];
    const float* A_log      = (const float*)d_in[4];
    const float* D_param    = (const float*)d_in[5];
    const float* x_proj_w   = (const float*)d_in[6];
    const float* dt_proj_w  = (const float*)d_in[7];
    const float* dt_proj_b  = (const float*)d_in[8];
    const float* out_proj_w = (const float*)d_in[9];
    float* out = (float*)d_out;

    float *xp, *zb, *xc, *xdbl, *dtb, *yb, *Pb, *Hb, *Hinb;
    cudaGetSymbolAddress((void**)&xp,   g_xp);
    cudaGetSymbolAddress((void**)&zb,   g_z);
    cudaGetSymbolAddress((void**)&xc,   g_xc);
    cudaGetSymbolAddress((void**)&xdbl, g_xdbl);
    cudaGetSymbolAddress((void**)&dtb,  g_dt);
    cudaGetSymbolAddress((void**)&yb,   g_y);
    cudaGetSymbolAddress((void**)&Pb,   g_P);
    cudaGetSymbolAddress((void**)&Hb,   g_H);
    cudaGetSymbolAddress((void**)&Hinb, g_Hin);

    // 1. xz = x @ in_proj_w^T, split -> xp, z   (tf32 tensor cores)
    {
        dim3 grid(2*DI/128, MROWS/128);
        gemm_tf32<1><<<grid, 256>>>(x, in_proj_w, xp, zb, MROWS, 2*DI, DM);
    }
    // 2. causal depthwise conv + bias + SiLU -> xc
    {
        int total = MROWS * DI;
        conv_silu_kernel<<<(total + 255)/256, 256>>>(xp, conv_w, conv_b, xc);
    }
    // 3. x_dbl = xc @ x_proj_w^T
    gemm_xdbl<<<MROWS/32, 256>>>(xc, x_proj_w, xdbl);
    // 4. dt = softplus(dt_low @ dt_proj_w^T + b)
    {
        dim3 grid(DI/128, MROWS/64);
        gemm_dt<<<grid, 256>>>(xdbl, dt_proj_w, dt_proj_b, dtb);
    }
    // 5. chunked selective scan
    scan_pass1<<<(NCHAN*NCH)/8, 128>>>(xdbl, dtb, xc, A_log, Pb, Hb);
    scan_combine<<<(NCHAN*DS + 255)/256, 256>>>(Pb, Hb, Hinb);
    scan_pass2<<<(NCHAN*NCH)/8, 128>>>(xdbl, dtb, xc, zb, A_log, D_param, Hinb, yb);
    // 6. out = y @ out_proj_w^T   (tf32 tensor cores)
    {
        dim3 grid(DM/128, MROWS/128);
        gemm_tf32<0><<<grid, 256>>>(yb, out_proj_w, out, nullptr, MROWS, DM, DI);
    }
}